// round 14
// baseline (speedup 1.0000x reference)
#include <cuda_runtime.h>
#include <cstdint>

// GRU B=64,T=4096,F=100,H=200,O=1. R12 base (best 7405us), 32 clusters x 4 CTAs, 320 thr.
// Deltas: (1) h in rank-chunked layout (4x52); (2) warps whose K-half holds the own-rank
// chunk run those 13 dot iterations BEFORE the cluster wait (hides rendezvous latency);
// (3) hold kept in a register; (4) 3 nops so ncu (2 hidden launches, capture #6) hits gru.

#define Bq      64
#define Tq      4096
#define Fq      100
#define Hq      200
#define G3      600
#define BT      (Bq * Tq)
#define CLUSTER 4
#define BG      2
#define JPC     50
#define NTHR    320
#define KHH     104              // K-half of padded 208 (= chunks {2kh,2kh+1} of 52)
#define TT      32               // phase-A tile rows
#define GRID    128

__device__ float g_gx[(size_t)GRID * Tq * BG * 160];   // CTA-private [t][b][160]
__device__ float g_h [(size_t)BT * Hq];                // [row=b*Tq+t][200]
__device__ int   g_dummy;

__device__ __forceinline__ uint32_t smem_u32(const void* p) {
    return (uint32_t)__cvta_generic_to_shared(p);
}
__device__ __forceinline__ void st_cluster_f32(uint32_t laddr, uint32_t rr, float v) {
    uint32_t ra;
    asm volatile("mapa.shared::cluster.u32 %0, %1, %2;" : "=r"(ra) : "r"(laddr), "r"(rr));
    asm volatile("st.shared::cluster.f32 [%0], %1;" :: "r"(ra), "f"(v) : "memory");
}
__device__ __forceinline__ void ffma2(unsigned long long& acc,
                                      unsigned long long a, unsigned long long b) {
    asm("fma.rn.f32x2 %0, %1, %2, %0;" : "+l"(acc) : "l"(a), "l"(b));
}
__device__ __forceinline__ float fold2(unsigned long long a, unsigned long long b) {
    unsigned long long s;
    asm("add.rn.f32x2 %0, %1, %2;" : "=l"(s) : "l"(a), "l"(b));
    return __uint_as_float((unsigned)s) + __uint_as_float((unsigned)(s >> 32));
}
__device__ __forceinline__ unsigned long long pack2(float a, float b) {
    return (unsigned long long)__float_as_uint(a) |
           ((unsigned long long)__float_as_uint(b) << 32);
}
__device__ __forceinline__ float tanh_fast(float x) {
    float t;
    asm("tanh.approx.f32 %0, %1;" : "=f"(t) : "f"(x));
    return t;
}
__device__ __forceinline__ float sigf(float x) {
    return 0.5f * tanh_fast(0.5f * x) + 0.5f;
}

struct __align__(16) Smem {
    float h[2][BG][208];        // parity, batch: 4 chunks of 52 (50 real + 2 zero pad)
    float gh[2][BG][160];       // K-half partials [kh][b][col]
    float bi_s[160];
    float bhn_s[64];
    float xs[BG][TT][104];      // phase-A staging (pads 100..103 zeroed)
};

__global__ void nop_kernel() {
    if (threadIdx.x == 1024) g_dummy = 1;
}

__global__ void __launch_bounds__(NTHR, 1)
gru_kernel(const float* __restrict__ x,  const float* __restrict__ Wi,
           const float* __restrict__ bi, const float* __restrict__ Wh,
           const float* __restrict__ bhn)
{
    extern __shared__ char smraw[];
    Smem* sm = reinterpret_cast<Smem*>(smraw);
    const int tid = threadIdx.x;
    uint32_t rank;
    asm("mov.u32 %0, %%cluster_ctarank;" : "=r"(rank));
    const int b0g = (blockIdx.x >> 2) * BG;
    float* gsl = &g_gx[(size_t)blockIdx.x * Tq * (BG * 160)];

    // ---- one-time SMEM init ----
    for (int i = tid; i < 2 * BG * 208; i += NTHR)
        (&sm->h[0][0][0])[i] = 0.f;
    for (int i = tid; i < 160; i += NTHR) {
        float v = 0.f;
        if (i < 150) { int g = i / JPC, jj = i - g * JPC; v = bi[g * Hq + (int)rank * JPC + jj]; }
        sm->bi_s[i] = v;
    }
    if (tid < JPC) sm->bhn_s[tid] = bhn[(int)rank * JPC + tid];
    for (int i = tid; i < BG * TT * 4; i += NTHR) {
        int b2 = i / (TT * 4), rem = i - b2 * (TT * 4);
        sm->xs[b2][rem >> 2][100 + (rem & 3)] = 0.f;
    }

    // ================= Phase A: gx = x · Wi (CTA-private slice) =================
    {
        const int c   = tid >> 1;        // 0..159 (c<150 real)
        const int b   = tid & 1;
        const bool act = (c < 150);
        int gcol = 0;
        if (act) { int g = c / JPC, j2 = c - g * JPC; gcol = g * Hq + (int)rank * JPC + j2; }

        ulonglong2 wr[26];               // k = 0..103 (100 real + 4 zero pad)
        #pragma unroll
        for (int q = 0; q < 26; ++q) {
            float v[4];
            #pragma unroll
            for (int r = 0; r < 4; ++r) {
                int k = q * 4 + r;
                v[r] = (act && k < Fq) ? Wi[(size_t)k * G3 + gcol] : 0.f;
            }
            wr[q].x = pack2(v[0], v[1]);
            wr[q].y = pack2(v[2], v[3]);
        }

        for (int t0 = 0; t0 < Tq; t0 += TT) {
            __syncthreads();
            for (int i = tid; i < BG * TT * Fq; i += NTHR) {
                int b2 = i / (TT * Fq), rem = i - b2 * (TT * Fq);
                int r = rem / Fq, f = rem - r * Fq;
                sm->xs[b2][r][f] =
                    x[(size_t)(b0g + b2) * (Tq * Fq) + (size_t)(t0 + r) * Fq + f];
            }
            __syncthreads();
            if (act) {
                for (int r = 0; r < TT; ++r) {
                    const ulonglong2* vp = reinterpret_cast<const ulonglong2*>(sm->xs[b][r]);
                    unsigned long long a0 = 0, a1 = 0;
                    #pragma unroll
                    for (int q = 0; q < 26; ++q) {
                        ulonglong2 v = vp[q];
                        ffma2(a0, wr[q].x, v.x);
                        ffma2(a1, wr[q].y, v.y);
                    }
                    gsl[(size_t)(t0 + r) * (BG * 160) + b * 160 + c] = fold2(a0, a1);
                }
            }
        }
    }
    __syncthreads();   // gsl visible CTA-wide

    // ================= Phase B: recurrence =================
    const int wid  = tid >> 5, lane = tid & 31;
    const int kh   = (wid >= 5);                         // K-half = chunks {2kh,2kh+1}
    const int col  = (kh ? wid - 5 : wid) * 32 + lane;   // 0..159 (150 real)
    // which 13-iteration block of my K-half is the own-rank chunk (-1 = none)
    const int ownq = ((int)rank == 2 * kh) ? 0 : (((int)rank == 2 * kh + 1) ? 1 : -1);

    // register-resident Wh, chunked layout: p = kh*104+4q+r -> chunk c2=p/52, w=p%52;
    // real h index = 50*c2 + w (w<50), pads zero.  (mapping verified in R11)
    ulonglong2 wreg[26];
    {
        int gcol = 0;
        const bool real = (col < 150);
        if (real) {
            int g = col / JPC, jj = col - g * JPC;
            gcol = g * Hq + (int)rank * JPC + jj;
        }
        #pragma unroll
        for (int q = 0; q < 26; ++q) {
            float v[4];
            #pragma unroll
            for (int r = 0; r < 4; ++r) {
                int p = kh * KHH + q * 4 + r;
                int c2 = p / 52, w = p - c2 * 52;
                v[r] = (real && w < 50) ? Wh[(size_t)(c2 * 50 + w) * G3 + gcol] : 0.f;
            }
            wreg[q].x = pack2(v[0], v[1]);
            wreg[q].y = pack2(v[2], v[3]);
        }
    }

    const int eb = tid >> 6, jj = tid & 63;      // epilogue map (tid<128, jj<50)
    const bool epi = (tid < 128) && (jj < JPC);
    const int jg  = (int)rank * JPC + jj;        // global h index (g_h layout)
    const int jsm = (int)rank * 52 + jj;         // chunked SMEM position
    const size_t gxo   = epi ? ((size_t)eb * 160 + jj) : 0;
    const size_t hbase = epi ? ((size_t)(b0g + eb) * Tq) * Hq + jg : 0;

    // 2-deep gx register pipeline
    float g0r = 0.f, g0z = 0.f, g0n = 0.f;
    float g1r = 0.f, g1z = 0.f, g1n = 0.f;
    if (epi) {
        g0r = gsl[gxo];       g0z = gsl[gxo + 50];       g0n = gsl[gxo + 100];
        const float* p = gsl + (BG * 160) + gxo;
        g1r = p[0];           g1z = p[50];               g1n = p[100];
    }
    float hp = 0.f;                              // own unit's previous h (register)

    __syncthreads();
    asm volatile("barrier.cluster.arrive.aligned;" ::: "memory");   // initial token

    int par = 0;
    for (int t = 0; t < Tq; ++t) {
        const int nxt = par ^ 1;

        const ulonglong2* vp0 = reinterpret_cast<const ulonglong2*>(&sm->h[par][0][kh * KHH]);
        const ulonglong2* vp1 = reinterpret_cast<const ulonglong2*>(&sm->h[par][1][kh * KHH]);
        unsigned long long a0x = 0, a0y = 0, a1x = 0, a1y = 0;

        // ---- dot part 1: own-rank chunk (local STS data, valid pre-rendezvous) ----
        if (ownq == 0) {
            #pragma unroll
            for (int q = 0; q < 13; ++q) {
                ulonglong2 v0 = vp0[q], v1 = vp1[q];
                ffma2(a0x, wreg[q].x, v0.x); ffma2(a0y, wreg[q].y, v0.y);
                ffma2(a1x, wreg[q].x, v1.x); ffma2(a1y, wreg[q].y, v1.y);
            }
        } else if (ownq == 1) {
            #pragma unroll
            for (int q = 13; q < 26; ++q) {
                ulonglong2 v0 = vp0[q], v1 = vp1[q];
                ffma2(a0x, wreg[q].x, v0.x); ffma2(a0y, wreg[q].y, v0.y);
                ffma2(a1x, wreg[q].x, v1.x); ffma2(a1y, wreg[q].y, v1.y);
            }
        }

        // all CTAs' h[par] pushes complete (also orders epilogue(t-1) vs peer reads)
        asm volatile("barrier.cluster.wait.aligned;" ::: "memory");

        // ---- dot part 2: remaining chunks ----
        if (ownq == 0) {
            #pragma unroll
            for (int q = 13; q < 26; ++q) {
                ulonglong2 v0 = vp0[q], v1 = vp1[q];
                ffma2(a0x, wreg[q].x, v0.x); ffma2(a0y, wreg[q].y, v0.y);
                ffma2(a1x, wreg[q].x, v1.x); ffma2(a1y, wreg[q].y, v1.y);
            }
        } else if (ownq == 1) {
            #pragma unroll
            for (int q = 0; q < 13; ++q) {
                ulonglong2 v0 = vp0[q], v1 = vp1[q];
                ffma2(a0x, wreg[q].x, v0.x); ffma2(a0y, wreg[q].y, v0.y);
                ffma2(a1x, wreg[q].x, v1.x); ffma2(a1y, wreg[q].y, v1.y);
            }
        } else {
            #pragma unroll
            for (int q = 0; q < 26; ++q) {
                ulonglong2 v0 = vp0[q], v1 = vp1[q];
                ffma2(a0x, wreg[q].x, v0.x); ffma2(a0y, wreg[q].y, v0.y);
                ffma2(a1x, wreg[q].x, v1.x); ffma2(a1y, wreg[q].y, v1.y);
            }
        }
        sm->gh[kh][0][col] = fold2(a0x, a0y);
        sm->gh[kh][1][col] = fold2(a1x, a1y);
        __syncthreads();

        // ---- epilogue: gates, h update, DSMEM exchange ----
        float hnew = 0.f;
        if (epi) {
            int cr = jj, cz = JPC + jj, cn = 2 * JPC + jj;
            float ar  = g0r + sm->gh[0][eb][cr] + sm->gh[1][eb][cr] + sm->bi_s[cr];
            float az  = g0z + sm->gh[0][eb][cz] + sm->gh[1][eb][cz] + sm->bi_s[cz];
            float ghn = sm->gh[0][eb][cn] + sm->gh[1][eb][cn] + sm->bhn_s[jj];
            float r = sigf(ar), z = sigf(az);
            float n = tanh_fast(g0n + sm->bi_s[cn] + r * ghn);
            hnew = n + z * (hp - n);
            hp = hnew;
            sm->h[nxt][eb][jsm] = hnew;              // own rank: plain STS
            uint32_t la = smem_u32(&sm->h[nxt][eb][jsm]);
            #pragma unroll
            for (uint32_t rr = 1; rr < CLUSTER; ++rr)
                st_cluster_f32(la, (rank + rr) & 3u, hnew);
        }
        __syncthreads();                             // all pushes issued

        asm volatile("barrier.cluster.arrive.aligned;" ::: "memory");

        // off the inter-CTA critical path
        if (epi) g_h[hbase + (size_t)t * Hq] = hnew;
        g0r = g1r; g0z = g1z; g0n = g1n;
        if (epi && (t + 2 < Tq)) {
            const float* p = gsl + (size_t)(t + 2) * (BG * 160) + gxo;
            g1r = p[0]; g1z = p[50]; g1n = p[100];
        }
        par = nxt;
    }
    asm volatile("barrier.cluster.wait.aligned;" ::: "memory");   // balance final arrive
}

// ================= Phase C: y = h · Wo + bo =================
__global__ void __launch_bounds__(256)
y_kernel(const float* __restrict__ Wo, const float* __restrict__ bo,
         float* __restrict__ out)
{
    __shared__ float wos[Hq];
    const int tid = threadIdx.x;
    if (tid < Hq) wos[tid] = Wo[tid];
    __syncthreads();
    const float bo0 = bo[0];
    const int lane = tid & 31;
    const int gw   = (blockIdx.x * 256 + tid) >> 5;
    const int nw   = (gridDim.x * 256) >> 5;
    for (int row = gw; row < BT; row += nw) {
        const float* hr = g_h + (size_t)row * Hq;
        float s = 0.f;
        #pragma unroll
        for (int k = lane; k < Hq; k += 32) s = fmaf(hr[k], wos[k], s);
        #pragma unroll
        for (int m = 16; m > 0; m >>= 1) s += __shfl_xor_sync(0xffffffffu, s, m);
        if (lane == 0) out[row] = s + bo0;
    }
}

extern "C" void kernel_launch(void* const* d_in, const int* in_sizes, int n_in,
                              void* d_out, int out_size) {
    (void)in_sizes; (void)n_in; (void)out_size;
    const float* x   = (const float*)d_in[0];
    const float* Wi  = (const float*)d_in[1];
    const float* bi  = (const float*)d_in[2];
    const float* Wh  = (const float*)d_in[3];
    const float* bhn = (const float*)d_in[4];
    const float* Wo  = (const float*)d_in[5];
    const float* bo  = (const float*)d_in[6];
    float* out = (float*)d_out;

    // 3 nops: with 2 hidden harness launches, gru_kernel lands at capture slot #6
    for (int i = 0; i < 3; ++i) nop_kernel<<<1, 32>>>();

    cudaFuncSetAttribute(gru_kernel, cudaFuncAttributeMaxDynamicSharedMemorySize,
                         (int)sizeof(Smem));
    cudaLaunchConfig_t cfg = {};
    cfg.gridDim  = dim3(GRID, 1, 1);
    cfg.blockDim = dim3(NTHR, 1, 1);
    cfg.dynamicSmemBytes = sizeof(Smem);
    cfg.stream = 0;
    cudaLaunchAttribute attr[1];
    attr[0].id = cudaLaunchAttributeClusterDimension;
    attr[0].val.clusterDim.x = CLUSTER;
    attr[0].val.clusterDim.y = 1;
    attr[0].val.clusterDim.z = 1;
    cfg.attrs = attr;
    cfg.numAttrs = 1;
    cudaLaunchKernelEx(&cfg, gru_kernel, x, Wi, bi, Wh, bhn);

    y_kernel<<<592, 256>>>(Wo, bo, out);
}

// round 15
// speedup vs baseline: 1.0599x; 1.0599x over previous
#include <cuda_runtime.h>
#include <cstdint>

// GRU B=64,T=4096,F=100,H=200,O=1. R12 base (best 7405us), 32 clusters x 4 CTAs, 320 thr.
// Deltas vs R12: (1) NO sync before cluster.arrive (arrive releases each thread's own
// pushes; wait completion implies all epi threads arrived); (2) bi folded into gx at
// phase A (epilogue drops 3 LDS+3 FADD); (3) hold kept in a register (drops 1 LDS).

#define Bq      64
#define Tq      4096
#define Fq      100
#define Hq      200
#define G3      600
#define BT      (Bq * Tq)
#define CLUSTER 4
#define BG      2
#define JPC     50
#define NTHR    320
#define KHH     104              // K-half of padded 208
#define TT      32               // phase-A tile rows
#define GRID    128

__device__ float g_gx[(size_t)GRID * Tq * BG * 160];   // CTA-private [t][b][160]
__device__ float g_h [(size_t)BT * Hq];                // [row=b*Tq+t][200]
__device__ int   g_dummy;

__device__ __forceinline__ uint32_t smem_u32(const void* p) {
    return (uint32_t)__cvta_generic_to_shared(p);
}
__device__ __forceinline__ void st_cluster_f32(uint32_t laddr, uint32_t rr, float v) {
    uint32_t ra;
    asm volatile("mapa.shared::cluster.u32 %0, %1, %2;" : "=r"(ra) : "r"(laddr), "r"(rr));
    asm volatile("st.shared::cluster.f32 [%0], %1;" :: "r"(ra), "f"(v) : "memory");
}
__device__ __forceinline__ void ffma2(unsigned long long& acc,
                                      unsigned long long a, unsigned long long b) {
    asm("fma.rn.f32x2 %0, %1, %2, %0;" : "+l"(acc) : "l"(a), "l"(b));
}
__device__ __forceinline__ float fold2(unsigned long long a, unsigned long long b) {
    unsigned long long s;
    asm("add.rn.f32x2 %0, %1, %2;" : "=l"(s) : "l"(a), "l"(b));
    return __uint_as_float((unsigned)s) + __uint_as_float((unsigned)(s >> 32));
}
__device__ __forceinline__ unsigned long long pack2(float a, float b) {
    return (unsigned long long)__float_as_uint(a) |
           ((unsigned long long)__float_as_uint(b) << 32);
}
__device__ __forceinline__ float tanh_fast(float x) {
    float t;
    asm("tanh.approx.f32 %0, %1;" : "=f"(t) : "f"(x));
    return t;
}
__device__ __forceinline__ float sigf(float x) {
    return 0.5f * tanh_fast(0.5f * x) + 0.5f;
}

struct __align__(16) Smem {
    float h[2][BG][208];        // parity, batch (pads 200..207 zeroed)
    float gh[2][BG][160];       // K-half partials [kh][b][col]
    float bi_s[160];
    float bhn_s[64];
    float xs[BG][TT][104];      // phase-A staging (pads 100..103 zeroed)
};

__global__ void nop_kernel() {
    if (threadIdx.x == 1024) g_dummy = 1;
}

__global__ void __launch_bounds__(NTHR, 1)
gru_kernel(const float* __restrict__ x,  const float* __restrict__ Wi,
           const float* __restrict__ bi, const float* __restrict__ Wh,
           const float* __restrict__ bhn)
{
    extern __shared__ char smraw[];
    Smem* sm = reinterpret_cast<Smem*>(smraw);
    const int tid = threadIdx.x;
    uint32_t rank;
    asm("mov.u32 %0, %%cluster_ctarank;" : "=r"(rank));
    const int b0g = (blockIdx.x >> 2) * BG;
    float* gsl = &g_gx[(size_t)blockIdx.x * Tq * (BG * 160)];

    // ---- one-time SMEM init ----
    for (int i = tid; i < 2 * BG * 208; i += NTHR)
        (&sm->h[0][0][0])[i] = 0.f;
    for (int i = tid; i < 160; i += NTHR) {
        float v = 0.f;
        if (i < 150) { int g = i / JPC, jj = i - g * JPC; v = bi[g * Hq + (int)rank * JPC + jj]; }
        sm->bi_s[i] = v;
    }
    if (tid < JPC) sm->bhn_s[tid] = bhn[(int)rank * JPC + tid];
    for (int i = tid; i < BG * TT * 4; i += NTHR) {
        int b2 = i / (TT * 4), rem = i - b2 * (TT * 4);
        sm->xs[b2][rem >> 2][100 + (rem & 3)] = 0.f;
    }

    // ================= Phase A: gx = x · Wi + bi (CTA-private slice) =================
    {
        const int c   = tid >> 1;        // 0..159 (c<150 real)
        const int b   = tid & 1;
        const bool act = (c < 150);
        int gcol = 0;
        if (act) { int g = c / JPC, j2 = c - g * JPC; gcol = g * Hq + (int)rank * JPC + j2; }

        ulonglong2 wr[26];               // k = 0..103 (100 real + 4 zero pad)
        #pragma unroll
        for (int q = 0; q < 26; ++q) {
            float v[4];
            #pragma unroll
            for (int r = 0; r < 4; ++r) {
                int k = q * 4 + r;
                v[r] = (act && k < Fq) ? Wi[(size_t)k * G3 + gcol] : 0.f;
            }
            wr[q].x = pack2(v[0], v[1]);
            wr[q].y = pack2(v[2], v[3]);
        }

        for (int t0 = 0; t0 < Tq; t0 += TT) {
            __syncthreads();             // also orders bi_s before first use below
            for (int i = tid; i < BG * TT * Fq; i += NTHR) {
                int b2 = i / (TT * Fq), rem = i - b2 * (TT * Fq);
                int r = rem / Fq, f = rem - r * Fq;
                sm->xs[b2][r][f] =
                    x[(size_t)(b0g + b2) * (Tq * Fq) + (size_t)(t0 + r) * Fq + f];
            }
            __syncthreads();
            if (act) {
                const float bic = sm->bi_s[c];
                for (int r = 0; r < TT; ++r) {
                    const ulonglong2* vp = reinterpret_cast<const ulonglong2*>(sm->xs[b][r]);
                    unsigned long long a0 = 0, a1 = 0;
                    #pragma unroll
                    for (int q = 0; q < 26; ++q) {
                        ulonglong2 v = vp[q];
                        ffma2(a0, wr[q].x, v.x);
                        ffma2(a1, wr[q].y, v.y);
                    }
                    gsl[(size_t)(t0 + r) * (BG * 160) + b * 160 + c] = fold2(a0, a1) + bic;
                }
            }
        }
    }
    __syncthreads();   // gsl visible CTA-wide

    // ================= Phase B: recurrence =================
    const int wid  = tid >> 5, lane = tid & 31;
    const int kh   = (wid >= 5);                         // K-half
    const int col  = (kh ? wid - 5 : wid) * 32 + lane;   // 0..159 (150 real)

    // register-resident Wh: column col, K-half slice (104 floats = 104 regs)
    ulonglong2 wreg[26];
    {
        int gcol = 0;
        const bool real = (col < 150);
        if (real) {
            int g = col / JPC, jj = col - g * JPC;
            gcol = g * Hq + (int)rank * JPC + jj;
        }
        #pragma unroll
        for (int q = 0; q < 26; ++q) {
            float v[4];
            #pragma unroll
            for (int r = 0; r < 4; ++r) {
                int k = kh * KHH + q * 4 + r;
                v[r] = (real && k < Hq) ? Wh[(size_t)k * G3 + gcol] : 0.f;
            }
            wreg[q].x = pack2(v[0], v[1]);
            wreg[q].y = pack2(v[2], v[3]);
        }
    }

    const int eb = tid >> 6, jj = tid & 63;      // epilogue map (tid<128, jj<50)
    const bool epi = (tid < 128) && (jj < JPC);
    const int jg = (int)rank * JPC + jj;
    const size_t gxo   = epi ? ((size_t)eb * 160 + jj) : 0;
    const size_t hbase = epi ? ((size_t)(b0g + eb) * Tq) * Hq + jg : 0;

    // 2-deep gx register pipeline: g0 = gx(t), g1 = gx(t+1)   (bi already folded in)
    float g0r = 0.f, g0z = 0.f, g0n = 0.f;
    float g1r = 0.f, g1z = 0.f, g1n = 0.f;
    if (epi) {
        g0r = gsl[gxo];       g0z = gsl[gxo + 50];       g0n = gsl[gxo + 100];
        const float* p = gsl + (BG * 160) + gxo;
        g1r = p[0];           g1z = p[50];               g1n = p[100];
    }
    float hp = 0.f;                              // own unit's previous h (register)

    __syncthreads();
    asm volatile("barrier.cluster.arrive.aligned;" ::: "memory");   // initial token

    int par = 0;
    for (int t = 0; t < Tq; ++t) {
        const int nxt = par ^ 1;

        // all CTAs' h[par] pushes complete (each thread's arrive released its own)
        asm volatile("barrier.cluster.wait.aligned;" ::: "memory");

        // ---- dot: K-half, both batches, warp-uniform broadcast loads ----
        {
            const ulonglong2* vp0 = reinterpret_cast<const ulonglong2*>(&sm->h[par][0][kh * KHH]);
            const ulonglong2* vp1 = reinterpret_cast<const ulonglong2*>(&sm->h[par][1][kh * KHH]);
            unsigned long long a0x = 0, a0y = 0, a1x = 0, a1y = 0;
            #pragma unroll
            for (int q = 0; q < 26; ++q) {
                ulonglong2 v0 = vp0[q], v1 = vp1[q];
                ffma2(a0x, wreg[q].x, v0.x); ffma2(a0y, wreg[q].y, v0.y);
                ffma2(a1x, wreg[q].x, v1.x); ffma2(a1y, wreg[q].y, v1.y);
            }
            sm->gh[kh][0][col] = fold2(a0x, a0y);
            sm->gh[kh][1][col] = fold2(a1x, a1y);
        }
        __syncthreads();                         // gh visible to epilogue

        // ---- epilogue: gates, h update, DSMEM exchange ----
        float hnew = 0.f;
        if (epi) {
            int cr = jj, cz = JPC + jj, cn = 2 * JPC + jj;
            float ar  = g0r + sm->gh[0][eb][cr] + sm->gh[1][eb][cr];
            float az  = g0z + sm->gh[0][eb][cz] + sm->gh[1][eb][cz];
            float ghn = sm->gh[0][eb][cn] + sm->gh[1][eb][cn] + sm->bhn_s[jj];
            float r = sigf(ar), z = sigf(az);
            float n = tanh_fast(g0n + r * ghn);
            hnew = n + z * (hp - n);
            hp = hnew;
            sm->h[nxt][eb][jg] = hnew;           // own rank: plain STS
            uint32_t la = smem_u32(&sm->h[nxt][eb][jg]);
            #pragma unroll
            for (uint32_t rr = 1; rr < CLUSTER; ++rr)
                st_cluster_f32(la, (rank + rr) & 3u, hnew);
        }
        // per-thread release of this thread's own pushes; no intra-CTA sync needed:
        // dot(t+1) cannot start before the wait, which needs every epi arrive.
        asm volatile("barrier.cluster.arrive.aligned;" ::: "memory");

        // off the inter-CTA critical path
        if (epi) g_h[hbase + (size_t)t * Hq] = hnew;
        g0r = g1r; g0z = g1z; g0n = g1n;
        if (epi && (t + 2 < Tq)) {
            const float* p = gsl + (size_t)(t + 2) * (BG * 160) + gxo;
            g1r = p[0]; g1z = p[50]; g1n = p[100];
        }
        par = nxt;
    }
    asm volatile("barrier.cluster.wait.aligned;" ::: "memory");   // balance final arrive
}

// ================= Phase C: y = h · Wo + bo =================
__global__ void __launch_bounds__(256)
y_kernel(const float* __restrict__ Wo, const float* __restrict__ bo,
         float* __restrict__ out)
{
    __shared__ float wos[Hq];
    const int tid = threadIdx.x;
    if (tid < Hq) wos[tid] = Wo[tid];
    __syncthreads();
    const float bo0 = bo[0];
    const int lane = tid & 31;
    const int gw   = (blockIdx.x * 256 + tid) >> 5;
    const int nw   = (gridDim.x * 256) >> 5;
    for (int row = gw; row < BT; row += nw) {
        const float* hr = g_h + (size_t)row * Hq;
        float s = 0.f;
        #pragma unroll
        for (int k = lane; k < Hq; k += 32) s = fmaf(hr[k], wos[k], s);
        #pragma unroll
        for (int m = 16; m > 0; m >>= 1) s += __shfl_xor_sync(0xffffffffu, s, m);
        if (lane == 0) out[row] = s + bo0;
    }
}

extern "C" void kernel_launch(void* const* d_in, const int* in_sizes, int n_in,
                              void* d_out, int out_size) {
    (void)in_sizes; (void)n_in; (void)out_size;
    const float* x   = (const float*)d_in[0];
    const float* Wi  = (const float*)d_in[1];
    const float* bi  = (const float*)d_in[2];
    const float* Wh  = (const float*)d_in[3];
    const float* bhn = (const float*)d_in[4];
    const float* Wo  = (const float*)d_in[5];
    const float* bo  = (const float*)d_in[6];
    float* out = (float*)d_out;

    // 3 nops: with 2 hidden harness launches, gru_kernel lands at capture slot #6
    for (int i = 0; i < 3; ++i) nop_kernel<<<1, 32>>>();

    cudaFuncSetAttribute(gru_kernel, cudaFuncAttributeMaxDynamicSharedMemorySize,
                         (int)sizeof(Smem));
    cudaLaunchConfig_t cfg = {};
    cfg.gridDim  = dim3(GRID, 1, 1);
    cfg.blockDim = dim3(NTHR, 1, 1);
    cfg.dynamicSmemBytes = sizeof(Smem);
    cfg.stream = 0;
    cudaLaunchAttribute attr[1];
    attr[0].id = cudaLaunchAttributeClusterDimension;
    attr[0].val.clusterDim.x = CLUSTER;
    attr[0].val.clusterDim.y = 1;
    attr[0].val.clusterDim.z = 1;
    cfg.attrs = attr;
    cfg.numAttrs = 1;
    cudaLaunchKernelEx(&cfg, gru_kernel, x, Wi, bi, Wh, bhn);

    y_kernel<<<592, 256>>>(Wo, bo, out);
}

// round 16
// speedup vs baseline: 1.1168x; 1.0538x over previous
#include <cuda_runtime.h>
#include <cstdint>

// GRU B=64,T=4096,F=100,H=200,O=1. R12 base (best 7405us), 32 clusters x 4 CTAs, 320 thr.
// Deltas vs R12 (sync-before-arrive KEPT — R15 showed removing it costs ~370us):
//  (1) bi folded into gx at phase A (epilogue: -3 LDS, -3 FADD)
//  (2) hold kept in a register (epilogue: -1 LDS)
//  (3) gh paired layout [b][col][2] -> epilogue reads 3x LDS.64 instead of 6x LDS.32

#define Bq      64
#define Tq      4096
#define Fq      100
#define Hq      200
#define G3      600
#define BT      (Bq * Tq)
#define CLUSTER 4
#define BG      2
#define JPC     50
#define NTHR    320
#define KHH     104              // K-half of padded 208
#define TT      32               // phase-A tile rows
#define GRID    128

__device__ float g_gx[(size_t)GRID * Tq * BG * 160];   // CTA-private [t][b][160]
__device__ float g_h [(size_t)BT * Hq];                // [row=b*Tq+t][200]
__device__ int   g_dummy;

__device__ __forceinline__ uint32_t smem_u32(const void* p) {
    return (uint32_t)__cvta_generic_to_shared(p);
}
__device__ __forceinline__ void st_cluster_f32(uint32_t laddr, uint32_t rr, float v) {
    uint32_t ra;
    asm volatile("mapa.shared::cluster.u32 %0, %1, %2;" : "=r"(ra) : "r"(laddr), "r"(rr));
    asm volatile("st.shared::cluster.f32 [%0], %1;" :: "r"(ra), "f"(v) : "memory");
}
__device__ __forceinline__ void ffma2(unsigned long long& acc,
                                      unsigned long long a, unsigned long long b) {
    asm("fma.rn.f32x2 %0, %1, %2, %0;" : "+l"(acc) : "l"(a), "l"(b));
}
__device__ __forceinline__ float fold2(unsigned long long a, unsigned long long b) {
    unsigned long long s;
    asm("add.rn.f32x2 %0, %1, %2;" : "=l"(s) : "l"(a), "l"(b));
    return __uint_as_float((unsigned)s) + __uint_as_float((unsigned)(s >> 32));
}
__device__ __forceinline__ unsigned long long pack2(float a, float b) {
    return (unsigned long long)__float_as_uint(a) |
           ((unsigned long long)__float_as_uint(b) << 32);
}
__device__ __forceinline__ float tanh_fast(float x) {
    float t;
    asm("tanh.approx.f32 %0, %1;" : "=f"(t) : "f"(x));
    return t;
}
__device__ __forceinline__ float sigf(float x) {
    return 0.5f * tanh_fast(0.5f * x) + 0.5f;
}

struct __align__(16) Smem {
    float h[2][BG][208];        // parity, batch (pads 200..207 zeroed)
    float gh[BG][160][2];       // paired K-half partials [b][col][kh]
    float bi_s[160];
    float bhn_s[64];
    float xs[BG][TT][104];      // phase-A staging (pads 100..103 zeroed)
};

__global__ void nop_kernel() {
    if (threadIdx.x == 1024) g_dummy = 1;
}

__global__ void __launch_bounds__(NTHR, 1)
gru_kernel(const float* __restrict__ x,  const float* __restrict__ Wi,
           const float* __restrict__ bi, const float* __restrict__ Wh,
           const float* __restrict__ bhn)
{
    extern __shared__ char smraw[];
    Smem* sm = reinterpret_cast<Smem*>(smraw);
    const int tid = threadIdx.x;
    uint32_t rank;
    asm("mov.u32 %0, %%cluster_ctarank;" : "=r"(rank));
    const int b0g = (blockIdx.x >> 2) * BG;
    float* gsl = &g_gx[(size_t)blockIdx.x * Tq * (BG * 160)];

    // ---- one-time SMEM init ----
    for (int i = tid; i < 2 * BG * 208; i += NTHR)
        (&sm->h[0][0][0])[i] = 0.f;
    for (int i = tid; i < 160; i += NTHR) {
        float v = 0.f;
        if (i < 150) { int g = i / JPC, jj = i - g * JPC; v = bi[g * Hq + (int)rank * JPC + jj]; }
        sm->bi_s[i] = v;
    }
    if (tid < JPC) sm->bhn_s[tid] = bhn[(int)rank * JPC + tid];
    for (int i = tid; i < BG * TT * 4; i += NTHR) {
        int b2 = i / (TT * 4), rem = i - b2 * (TT * 4);
        sm->xs[b2][rem >> 2][100 + (rem & 3)] = 0.f;
    }

    // ================= Phase A: gx = x · Wi + bi (CTA-private slice) =================
    {
        const int c   = tid >> 1;        // 0..159 (c<150 real)
        const int b   = tid & 1;
        const bool act = (c < 150);
        int gcol = 0;
        if (act) { int g = c / JPC, j2 = c - g * JPC; gcol = g * Hq + (int)rank * JPC + j2; }

        ulonglong2 wr[26];               // k = 0..103 (100 real + 4 zero pad)
        #pragma unroll
        for (int q = 0; q < 26; ++q) {
            float v[4];
            #pragma unroll
            for (int r = 0; r < 4; ++r) {
                int k = q * 4 + r;
                v[r] = (act && k < Fq) ? Wi[(size_t)k * G3 + gcol] : 0.f;
            }
            wr[q].x = pack2(v[0], v[1]);
            wr[q].y = pack2(v[2], v[3]);
        }

        for (int t0 = 0; t0 < Tq; t0 += TT) {
            __syncthreads();             // also orders bi_s before its use below
            for (int i = tid; i < BG * TT * Fq; i += NTHR) {
                int b2 = i / (TT * Fq), rem = i - b2 * (TT * Fq);
                int r = rem / Fq, f = rem - r * Fq;
                sm->xs[b2][r][f] =
                    x[(size_t)(b0g + b2) * (Tq * Fq) + (size_t)(t0 + r) * Fq + f];
            }
            __syncthreads();
            if (act) {
                const float bic = sm->bi_s[c];
                for (int r = 0; r < TT; ++r) {
                    const ulonglong2* vp = reinterpret_cast<const ulonglong2*>(sm->xs[b][r]);
                    unsigned long long a0 = 0, a1 = 0;
                    #pragma unroll
                    for (int q = 0; q < 26; ++q) {
                        ulonglong2 v = vp[q];
                        ffma2(a0, wr[q].x, v.x);
                        ffma2(a1, wr[q].y, v.y);
                    }
                    gsl[(size_t)(t0 + r) * (BG * 160) + b * 160 + c] = fold2(a0, a1) + bic;
                }
            }
        }
    }
    __syncthreads();   // gsl visible CTA-wide

    // ================= Phase B: recurrence =================
    const int wid  = tid >> 5, lane = tid & 31;
    const int kh   = (wid >= 5);                         // K-half
    const int col  = (kh ? wid - 5 : wid) * 32 + lane;   // 0..159 (150 real)

    // register-resident Wh: column col, K-half slice (104 floats = 104 regs)
    ulonglong2 wreg[26];
    {
        int gcol = 0;
        const bool real = (col < 150);
        if (real) {
            int g = col / JPC, jj = col - g * JPC;
            gcol = g * Hq + (int)rank * JPC + jj;
        }
        #pragma unroll
        for (int q = 0; q < 26; ++q) {
            float v[4];
            #pragma unroll
            for (int r = 0; r < 4; ++r) {
                int k = kh * KHH + q * 4 + r;
                v[r] = (real && k < Hq) ? Wh[(size_t)k * G3 + gcol] : 0.f;
            }
            wreg[q].x = pack2(v[0], v[1]);
            wreg[q].y = pack2(v[2], v[3]);
        }
    }

    const int eb = tid >> 6, jj = tid & 63;      // epilogue map (tid<128, jj<50)
    const bool epi = (tid < 128) && (jj < JPC);
    const int jg = (int)rank * JPC + jj;
    const size_t gxo   = epi ? ((size_t)eb * 160 + jj) : 0;
    const size_t hbase = epi ? ((size_t)(b0g + eb) * Tq) * Hq + jg : 0;

    // 2-deep gx register pipeline (bi already folded in)
    float g0r = 0.f, g0z = 0.f, g0n = 0.f;
    float g1r = 0.f, g1z = 0.f, g1n = 0.f;
    if (epi) {
        g0r = gsl[gxo];       g0z = gsl[gxo + 50];       g0n = gsl[gxo + 100];
        const float* p = gsl + (BG * 160) + gxo;
        g1r = p[0];           g1z = p[50];               g1n = p[100];
    }
    float hp = 0.f;                              // own unit's previous h (register)

    __syncthreads();
    asm volatile("barrier.cluster.arrive.aligned;" ::: "memory");   // initial token

    int par = 0;
    for (int t = 0; t < Tq; ++t) {
        const int nxt = par ^ 1;

        // all CTAs' h[par] pushes complete; also orders epilogue(t-1) vs dot(t) in-CTA
        asm volatile("barrier.cluster.wait.aligned;" ::: "memory");

        // ---- dot: K-half, both batches, warp-uniform broadcast loads ----
        {
            const ulonglong2* vp0 = reinterpret_cast<const ulonglong2*>(&sm->h[par][0][kh * KHH]);
            const ulonglong2* vp1 = reinterpret_cast<const ulonglong2*>(&sm->h[par][1][kh * KHH]);
            unsigned long long a0x = 0, a0y = 0, a1x = 0, a1y = 0;
            #pragma unroll
            for (int q = 0; q < 26; ++q) {
                ulonglong2 v0 = vp0[q], v1 = vp1[q];
                ffma2(a0x, wreg[q].x, v0.x); ffma2(a0y, wreg[q].y, v0.y);
                ffma2(a1x, wreg[q].x, v1.x); ffma2(a1y, wreg[q].y, v1.y);
            }
            sm->gh[0][col][kh] = fold2(a0x, a0y);
            sm->gh[1][col][kh] = fold2(a1x, a1y);
        }
        __syncthreads();

        // ---- epilogue: gates, h update, DSMEM exchange ----
        float hnew = 0.f;
        if (epi) {
            int cr = jj, cz = JPC + jj, cn = 2 * JPC + jj;
            float2 pr = *reinterpret_cast<const float2*>(&sm->gh[eb][cr][0]);
            float2 pz = *reinterpret_cast<const float2*>(&sm->gh[eb][cz][0]);
            float2 pn = *reinterpret_cast<const float2*>(&sm->gh[eb][cn][0]);
            float r = sigf(g0r + pr.x + pr.y);
            float z = sigf(g0z + pz.x + pz.y);
            float n = tanh_fast(g0n + r * (pn.x + pn.y + sm->bhn_s[jj]));
            hnew = n + z * (hp - n);
            hp = hnew;
            sm->h[nxt][eb][jg] = hnew;           // own rank: plain STS
            uint32_t la = smem_u32(&sm->h[nxt][eb][jg]);
            #pragma unroll
            for (uint32_t rr = 1; rr < CLUSTER; ++rr)
                st_cluster_f32(la, (rank + rr) & 3u, hnew);
        }
        __syncthreads();                         // drains pushes; arrives are cheap

        asm volatile("barrier.cluster.arrive.aligned;" ::: "memory");

        // off the inter-CTA critical path
        if (epi) g_h[hbase + (size_t)t * Hq] = hnew;
        g0r = g1r; g0z = g1z; g0n = g1n;
        if (epi && (t + 2 < Tq)) {
            const float* p = gsl + (size_t)(t + 2) * (BG * 160) + gxo;
            g1r = p[0]; g1z = p[50]; g1n = p[100];
        }
        par = nxt;
    }
    asm volatile("barrier.cluster.wait.aligned;" ::: "memory");   // balance final arrive
}

// ================= Phase C: y = h · Wo + bo =================
__global__ void __launch_bounds__(256)
y_kernel(const float* __restrict__ Wo, const float* __restrict__ bo,
         float* __restrict__ out)
{
    __shared__ float wos[Hq];
    const int tid = threadIdx.x;
    if (tid < Hq) wos[tid] = Wo[tid];
    __syncthreads();
    const float bo0 = bo[0];
    const int lane = tid & 31;
    const int gw   = (blockIdx.x * 256 + tid) >> 5;
    const int nw   = (gridDim.x * 256) >> 5;
    for (int row = gw; row < BT; row += nw) {
        const float* hr = g_h + (size_t)row * Hq;
        float s = 0.f;
        #pragma unroll
        for (int k = lane; k < Hq; k += 32) s = fmaf(hr[k], wos[k], s);
        #pragma unroll
        for (int m = 16; m > 0; m >>= 1) s += __shfl_xor_sync(0xffffffffu, s, m);
        if (lane == 0) out[row] = s + bo0;
    }
}

extern "C" void kernel_launch(void* const* d_in, const int* in_sizes, int n_in,
                              void* d_out, int out_size) {
    (void)in_sizes; (void)n_in; (void)out_size;
    const float* x   = (const float*)d_in[0];
    const float* Wi  = (const float*)d_in[1];
    const float* bi  = (const float*)d_in[2];
    const float* Wh  = (const float*)d_in[3];
    const float* bhn = (const float*)d_in[4];
    const float* Wo  = (const float*)d_in[5];
    const float* bo  = (const float*)d_in[6];
    float* out = (float*)d_out;

    // 3 nops: with 2 hidden harness launches, gru_kernel lands at capture slot #6
    for (int i = 0; i < 3; ++i) nop_kernel<<<1, 32>>>();

    cudaFuncSetAttribute(gru_kernel, cudaFuncAttributeMaxDynamicSharedMemorySize,
                         (int)sizeof(Smem));
    cudaLaunchConfig_t cfg = {};
    cfg.gridDim  = dim3(GRID, 1, 1);
    cfg.blockDim = dim3(NTHR, 1, 1);
    cfg.dynamicSmemBytes = sizeof(Smem);
    cfg.stream = 0;
    cudaLaunchAttribute attr[1];
    attr[0].id = cudaLaunchAttributeClusterDimension;
    attr[0].val.clusterDim.x = CLUSTER;
    attr[0].val.clusterDim.y = 1;
    attr[0].val.clusterDim.z = 1;
    cfg.attrs = attr;
    cfg.numAttrs = 1;
    cudaLaunchKernelEx(&cfg, gru_kernel, x, Wi, bi, Wh, bhn);

    y_kernel<<<592, 256>>>(Wo, bo, out);
}